// round 6
// baseline (speedup 1.0000x reference)
#include <cuda_runtime.h>
#include <math.h>

#define B_    32
#define S_    1024
#define IN_   1024
#define H_    1024
#define NCTA  128

typedef unsigned long long ull;

// ---------------- device scratch (no allocation allowed) ----------------
__device__ float    g_H[2][B_][H_];      // ping-pong hidden state
__device__ unsigned g_flags[4][32];      // per batch-group step flags

// ---------------- helpers ----------------
__device__ __forceinline__ unsigned ld_rlx(const unsigned* p) {
    unsigned v;
    asm volatile("ld.relaxed.gpu.u32 %0, [%1];" : "=r"(v) : "l"(p));
    return v;
}
__device__ __forceinline__ void st_rel(unsigned* p, unsigned v) {
    asm volatile("st.global.release.gpu.u32 [%0], %1;" :: "l"(p), "r"(v));
}
__device__ __forceinline__ void fence_acq() {
    asm volatile("fence.acq_rel.gpu;" ::: "memory");
}
__device__ __forceinline__ ull fma2(ull a, ull b, ull c) {
    ull d;
    asm("fma.rn.f32x2 %0, %1, %2, %3;" : "=l"(d) : "l"(a), "l"(b), "l"(c));
    return d;
}
__device__ __forceinline__ ull add2(ull a, ull b) {
    ull d;
    asm("add.rn.f32x2 %0, %1, %2;" : "=l"(d) : "l"(a), "l"(b));
    return d;
}
__device__ __forceinline__ ull pack2(float x) {
    ull d;
    asm("mov.b64 %0, {%1, %1};" : "=l"(d) : "f"(x));
    return d;
}
__device__ __forceinline__ void unpack2(ull v, float& lo, float& hi) {
    asm("mov.b64 {%0, %1}, %2;" : "=f"(lo), "=f"(hi) : "l"(v));
}
// tanh via exp2+rcp: abs err ~5e-7, saturates correctly for large |x|
__device__ __forceinline__ float tanh_fast(float x) {
    float a = x * 2.88539008177792681472f;   // 2*log2(e)
    float e;
    asm("ex2.approx.f32 %0, %1;" : "=f"(e) : "f"(a));
    float d = e + 1.0f;
    float r;
    asm("rcp.approx.f32 %0, %1;" : "=f"(r) : "f"(d));
    return fmaf(-2.0f, r, 1.0f);
}

// ---------------- init: zero flags ----------------
__global__ void rnn_init_kernel() {
    int idx = blockIdx.x * blockDim.x + threadIdx.x;
    if (idx < 128) ((unsigned*)g_flags)[idx] = 0u;
}

// ---------------- Xp = X @ W_xh + b  (fp32 SGEMM, 128x128x8 tiles, f32x2) ----------------
__global__ void __launch_bounds__(256, 2) gemm_xp_kernel(
    const float* __restrict__ A,    // [32768, 1024]
    const float* __restrict__ Bm,   // [1024, 1024]
    const float* __restrict__ bias, // [1024]
    float* __restrict__ C)          // [32768, 1024]
{
    __shared__ float As[8][128];
    __shared__ float Bs[8][128];

    int tid  = threadIdx.x;
    int brow = blockIdx.y * 128;
    int bcol = blockIdx.x * 128;

    int arow = tid >> 1;
    int acol = (tid & 1) * 4;
    int brl  = tid >> 5;
    int bc4  = (tid & 31) * 4;
    int ty   = tid >> 4;
    int tx   = tid & 15;

    ull acc2[8][4];
#pragma unroll
    for (int i = 0; i < 8; i++)
#pragma unroll
        for (int j = 0; j < 4; j++) acc2[i][j] = 0ull;

    const float* Aptr = A + (size_t)(brow + arow) * IN_ + acol;
    const float* Bptr = Bm + (size_t)brl * H_ + bcol + bc4;

    for (int k0 = 0; k0 < IN_; k0 += 8) {
        float4 a = *(const float4*)(Aptr + k0);
        As[acol + 0][arow] = a.x;
        As[acol + 1][arow] = a.y;
        As[acol + 2][arow] = a.z;
        As[acol + 3][arow] = a.w;
        *(float4*)&Bs[brl][bc4] = *(const float4*)(Bptr + (size_t)k0 * H_);
        __syncthreads();

#pragma unroll
        for (int k = 0; k < 8; k++) {
            float ar[8];
            *(float4*)(ar)     = *(float4*)&As[k][ty * 4];
            *(float4*)(ar + 4) = *(float4*)&As[k][64 + ty * 4];
            ull br2[4];
            br2[0] = *(const ull*)&Bs[k][tx * 4];
            br2[1] = *(const ull*)&Bs[k][tx * 4 + 2];
            br2[2] = *(const ull*)&Bs[k][64 + tx * 4];
            br2[3] = *(const ull*)&Bs[k][64 + tx * 4 + 2];
            ull ar2[8];
#pragma unroll
            for (int i = 0; i < 8; i++) ar2[i] = pack2(ar[i]);
#pragma unroll
            for (int i = 0; i < 8; i++)
#pragma unroll
                for (int j = 0; j < 4; j++)
                    acc2[i][j] = fma2(ar2[i], br2[j], acc2[i][j]);
        }
        __syncthreads();
    }

    float4 bv0 = *(const float4*)&bias[bcol + tx * 4];
    float4 bv1 = *(const float4*)&bias[bcol + 64 + tx * 4];
    float bb[8] = {bv0.x, bv0.y, bv0.z, bv0.w, bv1.x, bv1.y, bv1.z, bv1.w};

#pragma unroll
    for (int i = 0; i < 8; i++) {
        int m = brow + ((i < 4) ? (ty * 4 + i) : (64 + ty * 4 + (i - 4)));
        float o[8];
        unpack2(acc2[i][0], o[0], o[1]);
        unpack2(acc2[i][1], o[2], o[3]);
        unpack2(acc2[i][2], o[4], o[5]);
        unpack2(acc2[i][3], o[6], o[7]);
        float4 o0, o1;
        o0.x = o[0] + bb[0]; o0.y = o[1] + bb[1];
        o0.z = o[2] + bb[2]; o0.w = o[3] + bb[3];
        o1.x = o[4] + bb[4]; o1.y = o[5] + bb[5];
        o1.z = o[6] + bb[6]; o1.w = o[7] + bb[7];
        *(float4*)&C[(size_t)m * H_ + bcol + tx * 4]      = o0;
        *(float4*)&C[(size_t)m * H_ + bcol + 64 + tx * 4] = o1;
    }
}

// ---------------- recurrent scan ----------------
// 128 CTAs = 4 batch-groups (8 batches) x 32 col-groups (32 cols).
// Thread = (khalf, b, jpair). One output float2 per thread, fma2 inner loop.
// W SMEM layout: Wp[jp] = 1024 float2 {w[k][2jp], w[k][2jp+1]}, stride 2052
// floats (lane spacing 4 mod 32 -> conflict-free LDS.128 at full rate).
// H staged with row stride 1028 (b*4 mod 32 -> conflict-free broadcast).
#define WP_STRIDE   2052
#define WP_FLOATS   (16 * WP_STRIDE)         // 32832
#define HS_STRIDE   1028
#define HS_FLOATS   (8 * HS_STRIDE)          // 8224
#define RED_FLOATS  256
#define SCAN_SMEM_BYTES ((WP_FLOATS + HS_FLOATS + RED_FLOATS) * 4)

extern __shared__ float scan_smem[];

__global__ void __launch_bounds__(256, 1) rnn_scan_kernel(
    const float* __restrict__ Whh,   // [1024, 1024]
    float* __restrict__ out,         // [B,S,H] holds Xp on entry, H_t on exit
    int write_last)
{
    float* Ws  = scan_smem;                           // W pairs
    float* Hs  = scan_smem + WP_FLOATS;               // staged H rows
    float* red = scan_smem + WP_FLOATS + HS_FLOATS;   // khalf combine

    int tid = threadIdx.x;
    int cta = blockIdx.x;
    int bg  = cta >> 5;
    int cg  = cta & 31;
    int b0  = bg * 8;
    int j0  = cg * 32;

    // ---- preload W pairs: Ws[jp*2052 + 2k + {0,1}] = Whh[k][j0+2jp+{0,1}] ----
    for (int idx = tid; idx < 16 * H_; idx += 256) {
        int jp = idx & 15;
        int k  = idx >> 4;
        float2 w = *(const float2*)&Whh[(size_t)k * H_ + j0 + 2 * jp];
        *(float2*)&Ws[jp * WP_STRIDE + 2 * k] = w;
    }

    int khalf = tid >> 7;          // 0/1
    int r     = tid & 127;
    int b     = r >> 4;            // 0..7
    int jp    = r & 15;            // 0..15
    int kb    = khalf * 512;

    const unsigned* pollp = &g_flags[bg][tid >> 3];
    unsigned* relp = &g_flags[bg][cg];

    const float* wbase = Ws + jp * WP_STRIDE + kb * 2;
    const float* hbase = Hs + b * HS_STRIDE + kb;

    size_t oidx = ((size_t)(b0 + b) * S_) * H_ + j0 + 2 * jp;  // + t*H_ per step
    float v0 = 0.0f, v1 = 0.0f;

    // ---- step 0: H1 = tanh(Xp0), no matmul (H0 == 0) ----
    {
        if (tid < 128) {
            float2 xp = __ldcg((const float2*)&out[oidx]);
            v0 = tanh_fast(xp.x);
            v1 = tanh_fast(xp.y);
            *(float2*)&g_H[1][b0 + b][j0 + 2 * jp] = make_float2(v0, v1);
        }
        __syncthreads();
        if (tid == 0) st_rel(relp, 1u);
        if (tid < 128) *(float2*)&out[oidx] = make_float2(v0, v1);
    }

    for (int t = 1; t < S_; t++) {
        // prefetch this thread's Xp(t)
        float2 xp = make_float2(0.f, 0.f);
        if (tid < 128) xp = __ldcg((const float2*)&out[oidx + (size_t)t * H_]);

        // poll exactly the producer of the columns this thread stages
        while (ld_rlx(pollp) < (unsigned)t) { }
        fence_acq();

        // stage H(t) rows b0..b0+7 (L2, bypass L1), row stride 1028
        {
            const float4* Hsrc = (const float4*)(&g_H[t & 1][b0][0]);
            float4* Hdst = (float4*)Hs;
#pragma unroll
            for (int q = 0; q < 8; q++)
                Hdst[q * 257 + tid] = __ldcg(Hsrc + q * 256 + tid);
        }
        __syncthreads();

        // ---- inner: 512 k per thread, 8 k per iter, 2 accumulators ----
        ull acc_a = 0ull, acc_b = 0ull;
#pragma unroll 4
        for (int i = 0; i < 64; i++) {
            float4 h0 = *(const float4*)(hbase + i * 8);
            float4 h1 = *(const float4*)(hbase + i * 8 + 4);
            longlong2 w0 = *(const longlong2*)(wbase + i * 16);
            longlong2 w1 = *(const longlong2*)(wbase + i * 16 + 4);
            longlong2 w2 = *(const longlong2*)(wbase + i * 16 + 8);
            longlong2 w3 = *(const longlong2*)(wbase + i * 16 + 12);
            acc_a = fma2(pack2(h0.x), (ull)w0.x, acc_a);
            acc_b = fma2(pack2(h0.y), (ull)w0.y, acc_b);
            acc_a = fma2(pack2(h0.z), (ull)w1.x, acc_a);
            acc_b = fma2(pack2(h0.w), (ull)w1.y, acc_b);
            acc_a = fma2(pack2(h1.x), (ull)w2.x, acc_a);
            acc_b = fma2(pack2(h1.y), (ull)w2.y, acc_b);
            acc_a = fma2(pack2(h1.z), (ull)w3.x, acc_a);
            acc_b = fma2(pack2(h1.w), (ull)w3.y, acc_b);
        }
        ull acc = add2(acc_a, acc_b);

        // ---- khalf combine (2-way, via smem) ----
        if (khalf) *(ull*)&red[2 * r] = acc;
        __syncthreads();

        if (tid < 128) {
            acc = add2(acc, *(const ull*)&red[2 * r]);
            float lo, hi;
            unpack2(acc, lo, hi);
            v0 = tanh_fast(lo + xp.x);
            v1 = tanh_fast(hi + xp.y);
            *(float2*)&g_H[(t + 1) & 1][b0 + b][j0 + 2 * jp] = make_float2(v0, v1);
        }
        __syncthreads();
        if (tid == 0) st_rel(relp, (unsigned)(t + 1));

        // out stores after the release: off the critical path
        if (tid < 128) *(float2*)&out[oidx + (size_t)t * H_] = make_float2(v0, v1);
    }

    if (write_last && tid < 128)
        *(float2*)&out[(size_t)B_ * S_ * H_ + (size_t)(b0 + b) * H_ + j0 + 2 * jp] =
            make_float2(v0, v1);
}

// ---------------- launch ----------------
extern "C" void kernel_launch(void* const* d_in, const int* in_sizes, int n_in,
                              void* d_out, int out_size) {
    const float* X    = (const float*)d_in[0];
    const float* Wxh  = (const float*)d_in[1];
    const float* Whh  = (const float*)d_in[2];
    const float* bh   = (const float*)d_in[3];
    float* out        = (float*)d_out;

    // gemm first -> ncu's first-node capture profiles the GEMM next round
    dim3 gg(8, 256);
    gemm_xp_kernel<<<gg, 256>>>(X, Wxh, bh, out);

    rnn_init_kernel<<<1, 128>>>();

    cudaFuncSetAttribute(rnn_scan_kernel,
                         cudaFuncAttributeMaxDynamicSharedMemorySize,
                         SCAN_SMEM_BYTES);
    int write_last = (out_size >= B_ * S_ * H_ + B_ * H_) ? 1 : 0;
    rnn_scan_kernel<<<NCTA, 256, SCAN_SMEM_BYTES>>>(Whh, out, write_last);
}

// round 7
// speedup vs baseline: 1.7675x; 1.7675x over previous
#include <cuda_runtime.h>
#include <math.h>

#define B_    32
#define S_    1024
#define IN_   1024
#define H_    1024
#define NCTA  128

typedef unsigned long long ull;

// ---------------- device scratch (no allocation allowed) ----------------
__device__ float    g_H[2][B_][H_];      // ping-pong hidden state
__device__ unsigned g_flags[4][32];      // per batch-group step flags

// ---------------- helpers ----------------
__device__ __forceinline__ unsigned ld_acq(const unsigned* p) {
    unsigned v;
    asm volatile("ld.global.acquire.gpu.u32 %0, [%1];" : "=r"(v) : "l"(p));
    return v;
}
__device__ __forceinline__ void st_rel(unsigned* p, unsigned v) {
    asm volatile("st.global.release.gpu.u32 [%0], %1;" :: "l"(p), "r"(v));
}
__device__ __forceinline__ ull fma2(ull a, ull b, ull c) {
    ull d;
    asm("fma.rn.f32x2 %0, %1, %2, %3;" : "=l"(d) : "l"(a), "l"(b), "l"(c));
    return d;
}
__device__ __forceinline__ ull add2(ull a, ull b) {
    ull d;
    asm("add.rn.f32x2 %0, %1, %2;" : "=l"(d) : "l"(a), "l"(b));
    return d;
}
__device__ __forceinline__ ull pack2(float x) {
    ull d;
    asm("mov.b64 %0, {%1, %1};" : "=l"(d) : "f"(x));
    return d;
}
__device__ __forceinline__ ull pack2two(float lo, float hi) {
    ull d;
    asm("mov.b64 %0, {%1, %2};" : "=l"(d) : "f"(lo), "f"(hi));
    return d;
}
__device__ __forceinline__ void unpack2(ull v, float& lo, float& hi) {
    asm("mov.b64 {%0, %1}, %2;" : "=f"(lo), "=f"(hi) : "l"(v));
}
// tanh via exp2+rcp: abs err ~5e-7, saturates correctly for large |x|
__device__ __forceinline__ float tanh_fast(float x) {
    float a = x * 2.88539008177792681472f;   // 2*log2(e)
    float e;
    asm("ex2.approx.f32 %0, %1;" : "=f"(e) : "f"(a));
    float d = e + 1.0f;
    float r;
    asm("rcp.approx.f32 %0, %1;" : "=f"(r) : "f"(d));
    return fmaf(-2.0f, r, 1.0f);
}
__device__ __forceinline__ void cp_async16(void* smem_dst, const void* gsrc) {
    unsigned saddr = (unsigned)__cvta_generic_to_shared(smem_dst);
    asm volatile("cp.async.cg.shared.global [%0], [%1], 16;"
                 :: "r"(saddr), "l"(gsrc) : "memory");
}
__device__ __forceinline__ void cp_async_wait_all() {
    asm volatile("cp.async.wait_all;" ::: "memory");
}

// ---------------- init: zero H0 and flags ----------------
__global__ void rnn_init_kernel() {
    int idx = blockIdx.x * blockDim.x + threadIdx.x;
    int stride = gridDim.x * blockDim.x;
    float* p = &g_H[0][0][0];
    for (int i = idx; i < 2 * B_ * H_; i += stride) p[i] = 0.0f;
    if (idx < 128) ((unsigned*)g_flags)[idx] = 0u;
}

// ---------------- Xp = X @ W_xh + b  (fp32 SGEMM, double-buffered, f32x2) ----------------
__global__ void __launch_bounds__(256, 2) gemm_xp_kernel(
    const float* __restrict__ A,    // [32768, 1024]
    const float* __restrict__ Bm,   // [1024, 1024]
    const float* __restrict__ bias, // [1024]
    float* __restrict__ C)          // [32768, 1024]
{
    __shared__ float As[2][8][128];   // transposed A tile, double buffered
    __shared__ float Bs[2][8][128];

    int tid  = threadIdx.x;
    int brow = blockIdx.y * 128;
    int bcol = blockIdx.x * 128;

    int arow = tid >> 1;
    int acol = (tid & 1) * 4;
    int brl  = tid >> 5;
    int bc4  = (tid & 31) * 4;
    int ty   = tid >> 4;
    int tx   = tid & 15;

    ull acc2[8][4];
#pragma unroll
    for (int i = 0; i < 8; i++)
#pragma unroll
        for (int j = 0; j < 4; j++) acc2[i][j] = 0ull;

    const float* Aptr = A + (size_t)(brow + arow) * IN_ + acol;
    const float* Bptr = Bm + (size_t)brl * H_ + bcol + bc4;

    // prologue: slab 0 -> buf 0
    {
        float4 a = *(const float4*)Aptr;
        float4 b = *(const float4*)Bptr;
        As[0][acol + 0][arow] = a.x;
        As[0][acol + 1][arow] = a.y;
        As[0][acol + 2][arow] = a.z;
        As[0][acol + 3][arow] = a.w;
        *(float4*)&Bs[0][brl][bc4] = b;
    }
    __syncthreads();

    int p = 0;
    for (int s = 0; s < 128; s++) {
        float4 an, bn;
        if (s < 127) {  // prefetch next slab into registers during compute
            an = *(const float4*)(Aptr + (s + 1) * 8);
            bn = *(const float4*)(Bptr + (size_t)(s + 1) * 8 * H_);
        }
#pragma unroll
        for (int k = 0; k < 8; k++) {
            float ar[8];
            *(float4*)(ar)     = *(float4*)&As[p][k][ty * 4];
            *(float4*)(ar + 4) = *(float4*)&As[p][k][64 + ty * 4];
            ull br2[4];
            br2[0] = *(const ull*)&Bs[p][k][tx * 4];
            br2[1] = *(const ull*)&Bs[p][k][tx * 4 + 2];
            br2[2] = *(const ull*)&Bs[p][k][64 + tx * 4];
            br2[3] = *(const ull*)&Bs[p][k][64 + tx * 4 + 2];
            ull ar2[8];
#pragma unroll
            for (int i = 0; i < 8; i++) ar2[i] = pack2(ar[i]);
#pragma unroll
            for (int i = 0; i < 8; i++)
#pragma unroll
                for (int j = 0; j < 4; j++)
                    acc2[i][j] = fma2(ar2[i], br2[j], acc2[i][j]);
        }
        if (s < 127) {
            int q = p ^ 1;
            As[q][acol + 0][arow] = an.x;
            As[q][acol + 1][arow] = an.y;
            As[q][acol + 2][arow] = an.z;
            As[q][acol + 3][arow] = an.w;
            *(float4*)&Bs[q][brl][bc4] = bn;
        }
        __syncthreads();
        p ^= 1;
    }

    float4 bv0 = *(const float4*)&bias[bcol + tx * 4];
    float4 bv1 = *(const float4*)&bias[bcol + 64 + tx * 4];
    float bb[8] = {bv0.x, bv0.y, bv0.z, bv0.w, bv1.x, bv1.y, bv1.z, bv1.w};

#pragma unroll
    for (int i = 0; i < 8; i++) {
        int m = brow + ((i < 4) ? (ty * 4 + i) : (64 + ty * 4 + (i - 4)));
        float o[8];
        unpack2(acc2[i][0], o[0], o[1]);
        unpack2(acc2[i][1], o[2], o[3]);
        unpack2(acc2[i][2], o[4], o[5]);
        unpack2(acc2[i][3], o[6], o[7]);
        float4 o0, o1;
        o0.x = o[0] + bb[0]; o0.y = o[1] + bb[1];
        o0.z = o[2] + bb[2]; o0.w = o[3] + bb[3];
        o1.x = o[4] + bb[4]; o1.y = o[5] + bb[5];
        o1.z = o[6] + bb[6]; o1.w = o[7] + bb[7];
        *(float4*)&C[(size_t)m * H_ + bcol + tx * 4]      = o0;
        *(float4*)&C[(size_t)m * H_ + bcol + 64 + tx * 4] = o1;
    }
}

// ---------------- recurrent scan ----------------
// 128 CTAs = 4 batch-groups (8 batches) x 32 col-groups (32 cols).
// W_hh slice in SMEM j-major stride 1025 (conflict-free LDS.32 at full rate).
// Per warp: 8 batches x 8 cols tile, k split lane(32) x khalf(2).
#define WS_STRIDE  1025
#define WS_FLOATS  (32 * WS_STRIDE)          // 32800
#define HS_FLOATS  (8 * H_)                  // 8192
#define RED_STRIDE 72
#define RED_HALF   (4 * RED_STRIDE)          // 288
#define RED_FLOATS (2 * RED_HALF)            // 576
#define RNN_SMEM_BYTES ((WS_FLOATS + HS_FLOATS + RED_FLOATS) * 4)

extern __shared__ float rnn_smem[];

__global__ void __launch_bounds__(256, 1) rnn_scan_kernel(
    const float* __restrict__ Whh,   // [1024, 1024]
    float* __restrict__ out,         // [B,S,H] holds Xp on entry, H_t on exit
    int write_last)
{
    float* Ws  = rnn_smem;                        // [32][1025]  Ws[j][k]
    float* Hs  = rnn_smem + WS_FLOATS;            // [8][1024]
    float* red = rnn_smem + WS_FLOATS + HS_FLOATS;// [2][4][72]

    int tid = threadIdx.x;
    int cta = blockIdx.x;
    int bg  = cta >> 5;
    int cg  = cta & 31;
    int b0  = bg * 8;
    int j0  = cg * 32;

    // Preload W slice: Ws[j][k] = Whh[k][j0+j]. Coalesced LDG, conflict-free STS.
    {
        int j = tid & 31;
        for (int k = tid >> 5; k < H_; k += 8)
            Ws[j * WS_STRIDE + k] = Whh[(size_t)k * H_ + j0 + j];
    }

    int warp  = tid >> 5;
    int lane  = tid & 31;
    int jt    = warp >> 1;        // j-tile 0..3 (8 cols each)
    int khalf = warp & 1;         // k-half 0/1
    int kbase = khalf * 512;

    unsigned* myflags = g_flags[bg];

    // consumer mapping: thread owns output (b0+cb, j0+cc)
    int cb = tid >> 5;            // 0..7
    int cc = tid & 31;            // 0..31
    int cjt = cc >> 3;
    int cid = cb * 8 + (cc & 7);
    size_t out_base = ((size_t)(b0 + cb) * S_) * H_ + j0 + cc;   // + t*H_ per step

    const float* hp = Hs + kbase + lane;
    const float* wp = Ws + (size_t)(jt * 8) * WS_STRIDE + kbase + lane;

    __syncthreads();   // Ws ready

    for (int t = 0; t < S_; t++) {
        // ---- prefetch Xp(t) for this thread's output ----
        float xr = __ldcg(&out[out_base + (size_t)t * H_]);

        // ---- stage H rows for our 8 batches via cp.async (L1 bypass) ----
        {
            const float4* Hsrc = (const float4*)(&g_H[t & 1][b0][0]);
            float4* Hdst = (float4*)Hs;
#pragma unroll
            for (int q = 0; q < 8; q++)
                cp_async16(Hdst + tid + q * 256, Hsrc + tid + q * 256);
            cp_async_wait_all();
        }
        __syncthreads();

        // ---- main loop: 8 batches x 8 cols per warp, packed f32x2 FMA ----
        ull V[32];   // V[(bb<<2)|jj2] = acc pair (jj = 2*jj2, 2*jj2+1)
#pragma unroll
        for (int v = 0; v < 32; v++) V[v] = 0ull;

#pragma unroll
        for (int i = 0; i < 16; i++) {
            ull h2[8], w2[4];
#pragma unroll
            for (int b = 0; b < 8; b++)
                h2[b] = pack2(hp[b * H_ + i * 32]);
#pragma unroll
            for (int j2 = 0; j2 < 4; j2++) {
                float wlo = wp[(size_t)(2 * j2)     * WS_STRIDE + i * 32];
                float whi = wp[(size_t)(2 * j2 + 1) * WS_STRIDE + i * 32];
                w2[j2] = pack2two(wlo, whi);
            }
#pragma unroll
            for (int b = 0; b < 8; b++)
#pragma unroll
                for (int j2 = 0; j2 < 4; j2++)
                    V[(b << 2) | j2] = fma2(h2[b], w2[j2], V[(b << 2) | j2]);
        }

        // ---- split butterfly reduction over 32 k-lanes ----
        unsigned s;
        s = (lane >> 4) & 1;
        ull W1[16];
#pragma unroll
        for (int g = 0; g < 16; g++) {
            int vi = ((g >> 3) << 4) | (g & 7);
            ull snd = s ? V[vi] : V[vi | 8];
            ull kp  = s ? V[vi | 8] : V[vi];
            ull rcv = __shfl_xor_sync(0xffffffffu, snd, 16);
            W1[g] = add2(kp, rcv);
        }
        s = (lane >> 3) & 1;
        ull W2r[8];
#pragma unroll
        for (int g = 0; g < 8; g++) {
            int vi = ((g >> 2) << 3) | (g & 3);
            ull snd = s ? W1[vi] : W1[vi | 4];
            ull kp  = s ? W1[vi | 4] : W1[vi];
            ull rcv = __shfl_xor_sync(0xffffffffu, snd, 8);
            W2r[g] = add2(kp, rcv);
        }
        s = (lane >> 2) & 1;
        ull W3r[4];
#pragma unroll
        for (int g = 0; g < 4; g++) {
            int vi = ((g >> 1) << 2) | (g & 1);
            ull snd = s ? W2r[vi] : W2r[vi | 2];
            ull kp  = s ? W2r[vi | 2] : W2r[vi];
            ull rcv = __shfl_xor_sync(0xffffffffu, snd, 4);
            W3r[g] = add2(kp, rcv);
        }
        s = (lane >> 1) & 1;
        ull W4r[2];
#pragma unroll
        for (int g = 0; g < 2; g++) {
            int vi = g << 1;
            ull snd = s ? W3r[vi] : W3r[vi | 1];
            ull kp  = s ? W3r[vi | 1] : W3r[vi];
            ull rcv = __shfl_xor_sync(0xffffffffu, snd, 2);
            W4r[g] = add2(kp, rcv);
        }
        s = lane & 1;
        float fin[2];
#pragma unroll
        for (int r = 0; r < 2; r++) {
            float lo, hi;
            unpack2(W4r[r], lo, hi);
            float snd = s ? lo : hi;
            float kp  = s ? hi : lo;
            float rcv = __shfl_xor_sync(0xffffffffu, snd, 1);
            fin[r] = kp + rcv;
        }
        {
            float* redw = red + khalf * RED_HALF + jt * RED_STRIDE;
            redw[lane]      = fin[0];
            redw[lane + 32] = fin[1];
        }
        __syncthreads();

        // ---- per-thread tail: combine k-halves, tanh, publish ----
        float v = red[cjt * RED_STRIDE + cid] + red[RED_HALF + cjt * RED_STRIDE + cid];
        float val = tanh_fast(v + xr);
        g_H[(t + 1) & 1][b0 + cb][j0 + cc] = val;

        // ---- per batch-group barrier: release flag, then poll ----
        __syncthreads();
        if (tid == 0) st_rel(&myflags[cg], (unsigned)(t + 1));

        // out[] stores after the release: off the critical path
        out[out_base + (size_t)t * H_] = val;
        if (write_last && t == S_ - 1)
            out[(size_t)B_ * S_ * H_ + (size_t)(b0 + cb) * H_ + j0 + cc] = val;

        if (tid < 32) {
            while (ld_acq(&myflags[tid]) < (unsigned)(t + 1)) { }
        }
        __syncthreads();
    }
}

// ---------------- launch ----------------
extern "C" void kernel_launch(void* const* d_in, const int* in_sizes, int n_in,
                              void* d_out, int out_size) {
    const float* X    = (const float*)d_in[0];
    const float* Wxh  = (const float*)d_in[1];
    const float* Whh  = (const float*)d_in[2];
    const float* bh   = (const float*)d_in[3];
    float* out        = (float*)d_out;

    // scan-first in launch order? No: keep gemm first so ncu (first-node)
    // profiles the GEMM; init is tiny and runs concurrently-ish.
    rnn_init_kernel<<<64, 256>>>();

    dim3 gg(8, 256);
    gemm_xp_kernel<<<gg, 256>>>(X, Wxh, bh, out);

    cudaFuncSetAttribute(rnn_scan_kernel,
                         cudaFuncAttributeMaxDynamicSharedMemorySize,
                         RNN_SMEM_BYTES);
    int write_last = (out_size >= B_ * S_ * H_ + B_ * H_) ? 1 : 0;
    rnn_scan_kernel<<<NCTA, 256, RNN_SMEM_BYTES>>>(Whh, out, write_last);
}

// round 8
// speedup vs baseline: 3.0280x; 1.7132x over previous
#include <cuda_runtime.h>
#include <math.h>

#define B_    32
#define S_    1024
#define IN_   1024
#define H_    1024
#define NCTA  128

typedef unsigned long long ull;

// ---------------- device scratch (no allocation allowed) ----------------
__device__ float    g_H[2][B_][H_];      // ping-pong hidden state
// one 256B-stride line per (batch-group, col-group) flag: L2 hash bit7 is
// transparent, so 256B stride is needed to spread flags across LTS slices.
__device__ unsigned g_flags[4][32][64];

// ---------------- helpers ----------------
__device__ __forceinline__ unsigned ld_acq(const unsigned* p) {
    unsigned v;
    asm volatile("ld.global.acquire.gpu.u32 %0, [%1];" : "=r"(v) : "l"(p));
    return v;
}
__device__ __forceinline__ void st_rel(unsigned* p, unsigned v) {
    asm volatile("st.global.release.gpu.u32 [%0], %1;" :: "l"(p), "r"(v));
}
__device__ __forceinline__ ull fma2(ull a, ull b, ull c) {
    ull d;
    asm("fma.rn.f32x2 %0, %1, %2, %3;" : "=l"(d) : "l"(a), "l"(b), "l"(c));
    return d;
}
__device__ __forceinline__ ull add2(ull a, ull b) {
    ull d;
    asm("add.rn.f32x2 %0, %1, %2;" : "=l"(d) : "l"(a), "l"(b));
    return d;
}
__device__ __forceinline__ ull pack2(float x) {
    ull d;
    asm("mov.b64 %0, {%1, %1};" : "=l"(d) : "f"(x));
    return d;
}
__device__ __forceinline__ ull pack2two(float lo, float hi) {
    ull d;
    asm("mov.b64 %0, {%1, %2};" : "=l"(d) : "f"(lo), "f"(hi));
    return d;
}
__device__ __forceinline__ void unpack2(ull v, float& lo, float& hi) {
    asm("mov.b64 {%0, %1}, %2;" : "=f"(lo), "=f"(hi) : "l"(v));
}
// tanh via exp2+rcp: abs err ~5e-7, saturates correctly for large |x|
__device__ __forceinline__ float tanh_fast(float x) {
    float a = x * 2.88539008177792681472f;   // 2*log2(e)
    float e;
    asm("ex2.approx.f32 %0, %1;" : "=f"(e) : "f"(a));
    float d = e + 1.0f;
    float r;
    asm("rcp.approx.f32 %0, %1;" : "=f"(r) : "f"(d));
    return fmaf(-2.0f, r, 1.0f);
}
__device__ __forceinline__ void cp_async16(void* smem_dst, const void* gsrc) {
    unsigned saddr = (unsigned)__cvta_generic_to_shared(smem_dst);
    asm volatile("cp.async.cg.shared.global [%0], [%1], 16;"
                 :: "r"(saddr), "l"(gsrc) : "memory");
}
__device__ __forceinline__ void cp_async_wait_all() {
    asm volatile("cp.async.wait_all;" ::: "memory");
}

// ---------------- init: zero H0 and flags ----------------
__global__ void rnn_init_kernel() {
    int idx = blockIdx.x * blockDim.x + threadIdx.x;
    int stride = gridDim.x * blockDim.x;
    float* p = &g_H[0][0][0];
    for (int i = idx; i < 2 * B_ * H_; i += stride) p[i] = 0.0f;
    unsigned* f = &g_flags[0][0][0];
    for (int i = idx; i < 4 * 32 * 64; i += stride) f[i] = 0u;
}

// ---------------- Xp = X @ W_xh + b  (fp32 SGEMM, double-buffered, f32x2) ----------------
__global__ void __launch_bounds__(256, 2) gemm_xp_kernel(
    const float* __restrict__ A,    // [32768, 1024]
    const float* __restrict__ Bm,   // [1024, 1024]
    const float* __restrict__ bias, // [1024]
    float* __restrict__ C)          // [32768, 1024]
{
    __shared__ float As[2][8][128];   // transposed A tile, double buffered
    __shared__ float Bs[2][8][128];

    int tid  = threadIdx.x;
    int brow = blockIdx.y * 128;
    int bcol = blockIdx.x * 128;

    int arow = tid >> 1;
    int acol = (tid & 1) * 4;
    int brl  = tid >> 5;
    int bc4  = (tid & 31) * 4;
    int ty   = tid >> 4;
    int tx   = tid & 15;

    ull acc2[8][4];
#pragma unroll
    for (int i = 0; i < 8; i++)
#pragma unroll
        for (int j = 0; j < 4; j++) acc2[i][j] = 0ull;

    const float* Aptr = A + (size_t)(brow + arow) * IN_ + acol;
    const float* Bptr = Bm + (size_t)brl * H_ + bcol + bc4;

    // prologue: slab 0 -> buf 0
    {
        float4 a = *(const float4*)Aptr;
        float4 b = *(const float4*)Bptr;
        As[0][acol + 0][arow] = a.x;
        As[0][acol + 1][arow] = a.y;
        As[0][acol + 2][arow] = a.z;
        As[0][acol + 3][arow] = a.w;
        *(float4*)&Bs[0][brl][bc4] = b;
    }
    __syncthreads();

    int p = 0;
    for (int s = 0; s < 128; s++) {
        float4 an, bn;
        if (s < 127) {  // prefetch next slab into registers during compute
            an = *(const float4*)(Aptr + (s + 1) * 8);
            bn = *(const float4*)(Bptr + (size_t)(s + 1) * 8 * H_);
        }
#pragma unroll
        for (int k = 0; k < 8; k++) {
            float ar[8];
            *(float4*)(ar)     = *(float4*)&As[p][k][ty * 4];
            *(float4*)(ar + 4) = *(float4*)&As[p][k][64 + ty * 4];
            ull br2[4];
            br2[0] = *(const ull*)&Bs[p][k][tx * 4];
            br2[1] = *(const ull*)&Bs[p][k][tx * 4 + 2];
            br2[2] = *(const ull*)&Bs[p][k][64 + tx * 4];
            br2[3] = *(const ull*)&Bs[p][k][64 + tx * 4 + 2];
            ull ar2[8];
#pragma unroll
            for (int i = 0; i < 8; i++) ar2[i] = pack2(ar[i]);
#pragma unroll
            for (int i = 0; i < 8; i++)
#pragma unroll
                for (int j = 0; j < 4; j++)
                    acc2[i][j] = fma2(ar2[i], br2[j], acc2[i][j]);
        }
        if (s < 127) {
            int q = p ^ 1;
            As[q][acol + 0][arow] = an.x;
            As[q][acol + 1][arow] = an.y;
            As[q][acol + 2][arow] = an.z;
            As[q][acol + 3][arow] = an.w;
            *(float4*)&Bs[q][brl][bc4] = bn;
        }
        __syncthreads();
        p ^= 1;
    }

    float4 bv0 = *(const float4*)&bias[bcol + tx * 4];
    float4 bv1 = *(const float4*)&bias[bcol + 64 + tx * 4];
    float bb[8] = {bv0.x, bv0.y, bv0.z, bv0.w, bv1.x, bv1.y, bv1.z, bv1.w};

#pragma unroll
    for (int i = 0; i < 8; i++) {
        int m = brow + ((i < 4) ? (ty * 4 + i) : (64 + ty * 4 + (i - 4)));
        float o[8];
        unpack2(acc2[i][0], o[0], o[1]);
        unpack2(acc2[i][1], o[2], o[3]);
        unpack2(acc2[i][2], o[4], o[5]);
        unpack2(acc2[i][3], o[6], o[7]);
        float4 o0, o1;
        o0.x = o[0] + bb[0]; o0.y = o[1] + bb[1];
        o0.z = o[2] + bb[2]; o0.w = o[3] + bb[3];
        o1.x = o[4] + bb[4]; o1.y = o[5] + bb[5];
        o1.z = o[6] + bb[6]; o1.w = o[7] + bb[7];
        *(float4*)&C[(size_t)m * H_ + bcol + tx * 4]      = o0;
        *(float4*)&C[(size_t)m * H_ + bcol + 64 + tx * 4] = o1;
    }
}

// ---------------- recurrent scan ----------------
// 128 CTAs = 4 batch-groups (8 batches) x 32 col-groups (32 cols).
// W_hh slice in SMEM j-major stride 1025 (conflict-free LDS.32 at full rate).
// Per warp: 8 batches x 8 cols tile, k split lane(32) x khalf(2).
#define WS_STRIDE  1025
#define WS_FLOATS  (32 * WS_STRIDE)          // 32800
#define HS_FLOATS  (8 * H_)                  // 8192
#define RED_STRIDE 72
#define RED_HALF   (4 * RED_STRIDE)          // 288
#define RED_FLOATS (2 * RED_HALF)            // 576
#define RNN_SMEM_BYTES ((WS_FLOATS + HS_FLOATS + RED_FLOATS) * 4)

extern __shared__ float rnn_smem[];

__global__ void __launch_bounds__(256, 1) rnn_scan_kernel(
    const float* __restrict__ Whh,   // [1024, 1024]
    float* __restrict__ out,         // [B,S,H] holds Xp on entry, H_t on exit
    int write_last)
{
    float* Ws  = rnn_smem;                        // [32][1025]  Ws[j][k]
    float* Hs  = rnn_smem + WS_FLOATS;            // [8][1024]
    float* red = rnn_smem + WS_FLOATS + HS_FLOATS;// [2][4][72]

    int tid = threadIdx.x;
    int cta = blockIdx.x;
    int bg  = cta >> 5;
    int cg  = cta & 31;
    int b0  = bg * 8;
    int j0  = cg * 32;

    // Preload W slice: Ws[j][k] = Whh[k][j0+j]. Coalesced LDG, conflict-free STS.
    {
        int j = tid & 31;
        for (int k = tid >> 5; k < H_; k += 8)
            Ws[j * WS_STRIDE + k] = Whh[(size_t)k * H_ + j0 + j];
    }

    int warp  = tid >> 5;
    int lane  = tid & 31;
    int jt    = warp >> 1;        // j-tile 0..3 (8 cols each)
    int khalf = warp & 1;         // k-half 0/1
    int kbase = khalf * 512;

    // consumer mapping: thread owns output (b0+cb, j0+cc)
    int cb = tid >> 5;            // 0..7
    int cc = tid & 31;            // 0..31
    int cjt = cc >> 3;
    int cid = cb * 8 + (cc & 7);
    size_t out_base = ((size_t)(b0 + cb) * S_) * H_ + j0 + cc;   // + t*H_ per step

    const unsigned* pollp = &g_flags[bg][lane][0];   // lane polls its own line
    unsigned* relp = &g_flags[bg][cg][0];

    const float* hp = Hs + kbase + lane;
    const float* wp = Ws + (size_t)(jt * 8) * WS_STRIDE + kbase + lane;

    __syncthreads();   // Ws ready

    for (int t = 0; t < S_; t++) {
        // ---- prefetch Xp(t) for this thread's output ----
        float xr = __ldcg(&out[out_base + (size_t)t * H_]);

        // ---- stage H rows for our 8 batches via cp.async (L1 bypass) ----
        {
            const float4* Hsrc = (const float4*)(&g_H[t & 1][b0][0]);
            float4* Hdst = (float4*)Hs;
#pragma unroll
            for (int q = 0; q < 8; q++)
                cp_async16(Hdst + tid + q * 256, Hsrc + tid + q * 256);
            cp_async_wait_all();
        }
        __syncthreads();

        // ---- main loop: 8 batches x 8 cols per warp, packed f32x2 FMA ----
        ull V[32];   // V[(bb<<2)|jj2] = acc pair (jj = 2*jj2, 2*jj2+1)
#pragma unroll
        for (int v = 0; v < 32; v++) V[v] = 0ull;

#pragma unroll
        for (int i = 0; i < 16; i++) {
            ull h2[8], w2[4];
#pragma unroll
            for (int b = 0; b < 8; b++)
                h2[b] = pack2(hp[b * H_ + i * 32]);
#pragma unroll
            for (int j2 = 0; j2 < 4; j2++) {
                float wlo = wp[(size_t)(2 * j2)     * WS_STRIDE + i * 32];
                float whi = wp[(size_t)(2 * j2 + 1) * WS_STRIDE + i * 32];
                w2[j2] = pack2two(wlo, whi);
            }
#pragma unroll
            for (int b = 0; b < 8; b++)
#pragma unroll
                for (int j2 = 0; j2 < 4; j2++)
                    V[(b << 2) | j2] = fma2(h2[b], w2[j2], V[(b << 2) | j2]);
        }

        // ---- split butterfly reduction over 32 k-lanes ----
        unsigned s;
        s = (lane >> 4) & 1;
        ull W1[16];
#pragma unroll
        for (int g = 0; g < 16; g++) {
            int vi = ((g >> 3) << 4) | (g & 7);
            ull snd = s ? V[vi] : V[vi | 8];
            ull kp  = s ? V[vi | 8] : V[vi];
            ull rcv = __shfl_xor_sync(0xffffffffu, snd, 16);
            W1[g] = add2(kp, rcv);
        }
        s = (lane >> 3) & 1;
        ull W2r[8];
#pragma unroll
        for (int g = 0; g < 8; g++) {
            int vi = ((g >> 2) << 3) | (g & 3);
            ull snd = s ? W1[vi] : W1[vi | 4];
            ull kp  = s ? W1[vi | 4] : W1[vi];
            ull rcv = __shfl_xor_sync(0xffffffffu, snd, 8);
            W2r[g] = add2(kp, rcv);
        }
        s = (lane >> 2) & 1;
        ull W3r[4];
#pragma unroll
        for (int g = 0; g < 4; g++) {
            int vi = ((g >> 1) << 2) | (g & 1);
            ull snd = s ? W2r[vi] : W2r[vi | 2];
            ull kp  = s ? W2r[vi | 2] : W2r[vi];
            ull rcv = __shfl_xor_sync(0xffffffffu, snd, 4);
            W3r[g] = add2(kp, rcv);
        }
        s = (lane >> 1) & 1;
        ull W4r[2];
#pragma unroll
        for (int g = 0; g < 2; g++) {
            int vi = g << 1;
            ull snd = s ? W3r[vi] : W3r[vi | 1];
            ull kp  = s ? W3r[vi | 1] : W3r[vi];
            ull rcv = __shfl_xor_sync(0xffffffffu, snd, 2);
            W4r[g] = add2(kp, rcv);
        }
        s = lane & 1;
        float fin[2];
#pragma unroll
        for (int r = 0; r < 2; r++) {
            float lo, hi;
            unpack2(W4r[r], lo, hi);
            float snd = s ? lo : hi;
            float kp  = s ? hi : lo;
            float rcv = __shfl_xor_sync(0xffffffffu, snd, 1);
            fin[r] = kp + rcv;
        }
        {
            float* redw = red + khalf * RED_HALF + jt * RED_STRIDE;
            redw[lane]      = fin[0];
            redw[lane + 32] = fin[1];
        }
        __syncthreads();

        // ---- per-thread tail: combine k-halves, tanh, publish ----
        float v = red[cjt * RED_STRIDE + cid] + red[RED_HALF + cjt * RED_STRIDE + cid];
        float val = tanh_fast(v + xr);
        g_H[(t + 1) & 1][b0 + cb][j0 + cc] = val;

        // ---- per batch-group barrier: release own flag line, then poll ----
        __syncthreads();
        if (tid == 0) st_rel(relp, (unsigned)(t + 1));

        // out[] stores after the release: off the critical path
        out[out_base + (size_t)t * H_] = val;
        if (write_last && t == S_ - 1)
            out[(size_t)B_ * S_ * H_ + (size_t)(b0 + cb) * H_ + j0 + cc] = val;

        if (tid < 32) {
            while (ld_acq(pollp) < (unsigned)(t + 1)) { }
        }
        __syncthreads();
    }
}

// ---------------- launch ----------------
extern "C" void kernel_launch(void* const* d_in, const int* in_sizes, int n_in,
                              void* d_out, int out_size) {
    const float* X    = (const float*)d_in[0];
    const float* Wxh  = (const float*)d_in[1];
    const float* Whh  = (const float*)d_in[2];
    const float* bh   = (const float*)d_in[3];
    float* out        = (float*)d_out;

    rnn_init_kernel<<<64, 256>>>();

    dim3 gg(8, 256);
    gemm_xp_kernel<<<gg, 256>>>(X, Wxh, bh, out);

    cudaFuncSetAttribute(rnn_scan_kernel,
                         cudaFuncAttributeMaxDynamicSharedMemorySize,
                         RNN_SMEM_BYTES);
    int write_last = (out_size >= B_ * S_ * H_ + B_ * H_) ? 1 : 0;
    rnn_scan_kernel<<<NCTA, 256, RNN_SMEM_BYTES>>>(Whh, out, write_last);
}

// round 10
// speedup vs baseline: 3.2013x; 1.0572x over previous
#include <cuda_runtime.h>
#include <cuda_bf16.h>
#include <math.h>

#define B_    32
#define S_    1024
#define IN_   1024
#define H_    1024
#define NCTA  128

typedef unsigned long long ull;

// ---------------- device scratch (static, no dynamic allocation) ----------------
__device__ float    g_H[2][B_][H_];        // ping-pong hidden state
__device__ unsigned g_flags[4][32][64];    // one 256B line per (bg, cg)
__device__ __nv_bfloat16 g_Xhi[(size_t)B_ * S_ * IN_];   // [m][k]
__device__ __nv_bfloat16 g_Xlo[(size_t)B_ * S_ * IN_];
__device__ __nv_bfloat16 g_Whi[(size_t)IN_ * H_];        // [n][k] (W_xh transposed)
__device__ __nv_bfloat16 g_Wlo[(size_t)IN_ * H_];

// ---------------- generic helpers ----------------
__device__ __forceinline__ unsigned ld_acq(const unsigned* p) {
    unsigned v;
    asm volatile("ld.global.acquire.gpu.u32 %0, [%1];" : "=r"(v) : "l"(p));
    return v;
}
__device__ __forceinline__ void st_rel(unsigned* p, unsigned v) {
    asm volatile("st.global.release.gpu.u32 [%0], %1;" :: "l"(p), "r"(v));
}
__device__ __forceinline__ ull fma2(ull a, ull b, ull c) {
    ull d;
    asm("fma.rn.f32x2 %0, %1, %2, %3;" : "=l"(d) : "l"(a), "l"(b), "l"(c));
    return d;
}
__device__ __forceinline__ ull add2(ull a, ull b) {
    ull d;
    asm("add.rn.f32x2 %0, %1, %2;" : "=l"(d) : "l"(a), "l"(b));
    return d;
}
__device__ __forceinline__ ull pack2(float x) {
    ull d;
    asm("mov.b64 %0, {%1, %1};" : "=l"(d) : "f"(x));
    return d;
}
__device__ __forceinline__ ull pack2two(float lo, float hi) {
    ull d;
    asm("mov.b64 %0, {%1, %2};" : "=l"(d) : "f"(lo), "f"(hi));
    return d;
}
__device__ __forceinline__ void unpack2(ull v, float& lo, float& hi) {
    asm("mov.b64 {%0, %1}, %2;" : "=f"(lo), "=f"(hi) : "l"(v));
}
__device__ __forceinline__ float tanh_fast(float x) {
    float a = x * 2.88539008177792681472f;   // 2*log2(e)
    float e;
    asm("ex2.approx.f32 %0, %1;" : "=f"(e) : "f"(a));
    float d = e + 1.0f;
    float r;
    asm("rcp.approx.f32 %0, %1;" : "=f"(r) : "f"(d));
    return fmaf(-2.0f, r, 1.0f);
}
__device__ __forceinline__ void cp_async16(void* smem_dst, const void* gsrc) {
    unsigned saddr = (unsigned)__cvta_generic_to_shared(smem_dst);
    asm volatile("cp.async.cg.shared.global [%0], [%1], 16;"
                 :: "r"(saddr), "l"(gsrc) : "memory");
}
__device__ __forceinline__ void cp_async_wait_all() {
    asm volatile("cp.async.wait_all;" ::: "memory");
}
__device__ __forceinline__ void cp_async_commit() {
    asm volatile("cp.async.commit_group;" ::: "memory");
}
__device__ __forceinline__ void cp_async_wait0() {
    asm volatile("cp.async.wait_group 0;" ::: "memory");
}

// ---------------- mma helpers ----------------
__device__ __forceinline__ void ldmx4(unsigned& r0, unsigned& r1, unsigned& r2,
                                      unsigned& r3, unsigned saddr) {
    asm volatile("ldmatrix.sync.aligned.m8n8.x4.shared.b16 {%0,%1,%2,%3}, [%4];"
                 : "=r"(r0), "=r"(r1), "=r"(r2), "=r"(r3) : "r"(saddr));
}
#define MMA_BF16(d, a, b0v, b1v)                                              \
    asm volatile(                                                             \
        "mma.sync.aligned.m16n8k16.row.col.f32.bf16.bf16.f32 "                \
        "{%0,%1,%2,%3},{%4,%5,%6,%7},{%8,%9},{%0,%1,%2,%3};"                  \
        : "+f"((d)[0]), "+f"((d)[1]), "+f"((d)[2]), "+f"((d)[3])              \
        : "r"((a)[0]), "r"((a)[1]), "r"((a)[2]), "r"((a)[3]),                 \
          "r"(b0v), "r"(b1v))

// ---------------- conversion kernels (split bf16 hi/lo) ----------------
__global__ void conv_x_kernel(const float* __restrict__ X) {
    size_t i = (size_t)blockIdx.x * blockDim.x + threadIdx.x;   // float4 index
    const float4* src = (const float4*)X;
    float4 v = src[i];
    __nv_bfloat16 hv[4], lv[4];
    float vv[4] = {v.x, v.y, v.z, v.w};
#pragma unroll
    for (int j = 0; j < 4; j++) {
        hv[j] = __float2bfloat16(vv[j]);
        lv[j] = __float2bfloat16(vv[j] - __bfloat162float(hv[j]));
    }
    *(uint2*)&g_Xhi[i * 4] = *(uint2*)hv;
    *(uint2*)&g_Xlo[i * 4] = *(uint2*)lv;
}
__global__ void conv_w_kernel(const float* __restrict__ W) {
    int idx = blockIdx.x * blockDim.x + threadIdx.x;
    int n  = idx & 1023;
    int k0 = (idx >> 10) * 4;
    __nv_bfloat16 hv[4], lv[4];
#pragma unroll
    for (int j = 0; j < 4; j++) {
        float w = W[(size_t)(k0 + j) * H_ + n];
        hv[j] = __float2bfloat16(w);
        lv[j] = __float2bfloat16(w - __bfloat162float(hv[j]));
    }
    *(uint2*)&g_Whi[(size_t)n * IN_ + k0] = *(uint2*)hv;
    *(uint2*)&g_Wlo[(size_t)n * IN_ + k0] = *(uint2*)lv;
}

// ---------------- init: zero H0 and flags ----------------
__global__ void rnn_init_kernel() {
    int idx = blockIdx.x * blockDim.x + threadIdx.x;
    int stride = gridDim.x * blockDim.x;
    float* p = &g_H[0][0][0];
    for (int i = idx; i < 2 * B_ * H_; i += stride) p[i] = 0.0f;
    unsigned* f = &g_flags[0][0][0];
    for (int i = idx; i < 4 * 32 * 64; i += stride) f[i] = 0u;
}

// ---------------- HMMA split-bf16 GEMM: Xp = X @ W_xh + b ----------------
// 128x128 tile/CTA, k-slab 32 bf16, double-buffered cp.async.
// SMEM tiles [128][40] bf16 (80B row stride -> conflict-free ldmatrix).
#define GKS       32                 // k per slab
#define TROW      40                 // bf16 row stride
#define TILE_ELE  (128 * TROW)       // 5120 bf16 per tile
#define BUF_ELE   (4 * TILE_ELE)     // Ahi, Alo, Bhi, Blo
#define GEMM_SMEM (2 * BUF_ELE * 2)  // bytes = 81920

extern __shared__ __nv_bfloat16 gbuf[];

__global__ void __launch_bounds__(256, 1) gemm_bf16_kernel(
    const float* __restrict__ bias, float* __restrict__ C)
{
    int tid  = threadIdx.x;
    int wid  = tid >> 5;
    int lane = tid & 31;
    int brow = blockIdx.y * 128;
    int bcol = blockIdx.x * 128;

    int wm = wid >> 2;      // 0..1 (64 m-rows each)
    int wn = wid & 3;       // 0..3 (32 n-cols each)

    // ---- fill assignment: tile = tid>>6, rows (tid&63), (tid&63)+64 ----
    int tIdx = tid >> 6;
    int frow = tid & 63;
    const __nv_bfloat16* gsrc =
        (tIdx == 0) ? g_Xhi + (size_t)brow * IN_ :
        (tIdx == 1) ? g_Xlo + (size_t)brow * IN_ :
        (tIdx == 2) ? g_Whi + (size_t)bcol * IN_ :
                      g_Wlo + (size_t)bcol * IN_;
    __nv_bfloat16* dtile0 = gbuf + tIdx * TILE_ELE;

    auto fill = [&](int s, int buf) {
        __nv_bfloat16* dt = dtile0 + buf * BUF_ELE;
#pragma unroll
        for (int c = 0; c < 8; c++) {
            int row = frow + (c >> 2) * 64;
            int q   = c & 3;
            cp_async16(dt + row * TROW + q * 8,
                       gsrc + (size_t)row * IN_ + s * GKS + q * 8);
        }
    };

    // ---- ldmatrix lane address components ----
    int lrA = (lane & 7) + ((lane >> 3) & 1) * 8;   // A row in 16-frag
    int lkA = ((lane >> 4) & 1) * 8;                // A k offset
    int lnB = (lane & 7) + ((lane >> 4) & 1) * 8;   // B n in 16-pair
    int lkB = ((lane >> 3) & 1) * 8;                // B k offset

    unsigned sbase = (unsigned)__cvta_generic_to_shared(gbuf);
    // byte offsets
    unsigned offAhi = 0, offAlo = TILE_ELE * 2;
    unsigned offBhi = 2 * TILE_ELE * 2, offBlo = 3 * TILE_ELE * 2;

    float acc[4][4][4];
#pragma unroll
    for (int mi = 0; mi < 4; mi++)
#pragma unroll
        for (int ni = 0; ni < 4; ni++)
#pragma unroll
            for (int e = 0; e < 4; e++) acc[mi][ni][e] = 0.0f;

    fill(0, 0);
    cp_async_commit();

    for (int s = 0; s < IN_ / GKS; s++) {
        int buf = s & 1;
        cp_async_wait0();
        __syncthreads();
        if (s < IN_ / GKS - 1) {
            fill(s + 1, buf ^ 1);
            cp_async_commit();
        }
        unsigned bb = sbase + buf * (BUF_ELE * 2);

#pragma unroll
        for (int kk = 0; kk < GKS; kk += 16) {
            unsigned ah[4][4], al[4][4];
#pragma unroll
            for (int mi = 0; mi < 4; mi++) {
                unsigned ro = (unsigned)((wm * 64 + mi * 16 + lrA) * TROW + kk + lkA) * 2;
                ldmx4(ah[mi][0], ah[mi][1], ah[mi][2], ah[mi][3], bb + offAhi + ro);
                ldmx4(al[mi][0], al[mi][1], al[mi][2], al[mi][3], bb + offAlo + ro);
            }
            unsigned bh[2][4], bl[2][4];
#pragma unroll
            for (int np = 0; np < 2; np++) {
                unsigned ro = (unsigned)((wn * 32 + np * 16 + lnB) * TROW + kk + lkB) * 2;
                ldmx4(bh[np][0], bh[np][1], bh[np][2], bh[np][3], bb + offBhi + ro);
                ldmx4(bl[np][0], bl[np][1], bl[np][2], bl[np][3], bb + offBlo + ro);
            }
#pragma unroll
            for (int mi = 0; mi < 4; mi++)
#pragma unroll
                for (int ni = 0; ni < 4; ni++) {
                    int pr = ni >> 1, wh = (ni & 1) * 2;
                    MMA_BF16(acc[mi][ni], ah[mi], bh[pr][wh], bh[pr][wh + 1]);
                    MMA_BF16(acc[mi][ni], ah[mi], bl[pr][wh], bl[pr][wh + 1]);
                    MMA_BF16(acc[mi][ni], al[mi], bh[pr][wh], bh[pr][wh + 1]);
                }
        }
    }

    // ---- epilogue: add bias, store ----
    int gr = lane >> 2;
    int gc = (lane & 3) * 2;
#pragma unroll
    for (int ni = 0; ni < 4; ni++) {
        int col = bcol + wn * 32 + ni * 8 + gc;
        float2 bv = *(const float2*)&bias[col];
#pragma unroll
        for (int mi = 0; mi < 4; mi++) {
            int row0 = brow + wm * 64 + mi * 16 + gr;
            float2 o0 = make_float2(acc[mi][ni][0] + bv.x, acc[mi][ni][1] + bv.y);
            float2 o1 = make_float2(acc[mi][ni][2] + bv.x, acc[mi][ni][3] + bv.y);
            *(float2*)&C[(size_t)row0 * H_ + col]       = o0;
            *(float2*)&C[(size_t)(row0 + 8) * H_ + col] = o1;
        }
    }
}

// ---------------- recurrent scan (unchanged R8 champion) ----------------
#define WS_STRIDE  1025
#define WS_FLOATS  (32 * WS_STRIDE)
#define HS_FLOATS  (8 * H_)
#define RED_STRIDE 72
#define RED_HALF   (4 * RED_STRIDE)
#define RED_FLOATS (2 * RED_HALF)
#define RNN_SMEM_BYTES ((WS_FLOATS + HS_FLOATS + RED_FLOATS) * 4)

extern __shared__ float rnn_smem[];

__global__ void __launch_bounds__(256, 1) rnn_scan_kernel(
    const float* __restrict__ Whh,
    float* __restrict__ out,
    int write_last)
{
    float* Ws  = rnn_smem;
    float* Hs  = rnn_smem + WS_FLOATS;
    float* red = rnn_smem + WS_FLOATS + HS_FLOATS;

    int tid = threadIdx.x;
    int cta = blockIdx.x;
    int bg  = cta >> 5;
    int cg  = cta & 31;
    int b0  = bg * 8;
    int j0  = cg * 32;

    {
        int j = tid & 31;
        for (int k = tid >> 5; k < H_; k += 8)
            Ws[j * WS_STRIDE + k] = Whh[(size_t)k * H_ + j0 + j];
    }

    int warp  = tid >> 5;
    int lane  = tid & 31;
    int jt    = warp >> 1;
    int khalf = warp & 1;
    int kbase = khalf * 512;

    int cb = tid >> 5;
    int cc = tid & 31;
    int cjt = cc >> 3;
    int cid = cb * 8 + (cc & 7);
    size_t out_base = ((size_t)(b0 + cb) * S_) * H_ + j0 + cc;

    const unsigned* pollp = &g_flags[bg][lane][0];
    unsigned* relp = &g_flags[bg][cg][0];

    const float* hp = Hs + kbase + lane;
    const float* wp = Ws + (size_t)(jt * 8) * WS_STRIDE + kbase + lane;

    __syncthreads();

    for (int t = 0; t < S_; t++) {
        float xr = __ldcg(&out[out_base + (size_t)t * H_]);

        {
            const float4* Hsrc = (const float4*)(&g_H[t & 1][b0][0]);
            float4* Hdst = (float4*)Hs;
#pragma unroll
            for (int q = 0; q < 8; q++)
                cp_async16(Hdst + tid + q * 256, Hsrc + tid + q * 256);
            cp_async_wait_all();
        }
        __syncthreads();

        ull V[32];
#pragma unroll
        for (int v = 0; v < 32; v++) V[v] = 0ull;

#pragma unroll
        for (int i = 0; i < 16; i++) {
            ull h2[8], w2[4];
#pragma unroll
            for (int b = 0; b < 8; b++)
                h2[b] = pack2(hp[b * H_ + i * 32]);
#pragma unroll
            for (int j2 = 0; j2 < 4; j2++) {
                float wlo = wp[(size_t)(2 * j2)     * WS_STRIDE + i * 32];
                float whi = wp[(size_t)(2 * j2 + 1) * WS_STRIDE + i * 32];
                w2[j2] = pack2two(wlo, whi);
            }
#pragma unroll
            for (int b = 0; b < 8; b++)
#pragma unroll
                for (int j2 = 0; j2 < 4; j2++)
                    V[(b << 2) | j2] = fma2(h2[b], w2[j2], V[(b << 2) | j2]);
        }

        unsigned s;
        s = (lane >> 4) & 1;
        ull W1[16];
#pragma unroll
        for (int g = 0; g < 16; g++) {
            int vi = ((g >> 3) << 4) | (g & 7);
            ull snd = s ? V[vi] : V[vi | 8];
            ull kp  = s ? V[vi | 8] : V[vi];
            ull rcv = __shfl_xor_sync(0xffffffffu, snd, 16);
            W1[g] = add2(kp, rcv);
        }
        s = (lane >> 3) & 1;
        ull W2r[8];
#pragma unroll
        for (int g = 0; g < 8; g++) {
            int vi = ((g >> 2) << 3) | (g & 3);
            ull snd = s ? W1[vi] : W1[vi | 4];
            ull kp  = s ? W1[vi | 4] : W1[vi];
            ull rcv = __shfl_xor_sync(0xffffffffu, snd, 8);
            W2r[g] = add2(kp, rcv);
        }
        s = (lane >> 2) & 1;
        ull W3r[4];
#pragma unroll
        for (int g = 0; g < 4; g++) {
            int vi = ((g >> 1) << 2) | (g & 1);
            ull snd = s ? W2r[vi] : W2r[vi | 2];
            ull kp  = s ? W2r[vi | 2] : W2r[vi];
            ull rcv = __shfl_xor_sync(0xffffffffu, snd, 4);
            W3r[g] = add2(kp, rcv);
        }
        s = (lane >> 1) & 1;
        ull W4r[2];
#pragma unroll
        for (int g = 0; g < 2; g++) {
            int vi = g << 1;
            ull snd = s ? W3r[vi] : W3r[vi | 1];
            ull kp  = s ? W3r[vi | 1] : W3r[vi];
            ull rcv = __shfl_xor_sync(0xffffffffu, snd, 2);
            W4r[g] = add2(kp, rcv);
        }
        s = lane & 1;
        float fin[2];
#pragma unroll
        for (int r = 0; r < 2; r++) {
            float lo, hi;
            unpack2(W4r[r], lo, hi);
            float snd = s ? lo : hi;
            float kp  = s ? hi : lo;
            float rcv = __shfl_xor_sync(0xffffffffu, snd, 1);
            fin[r] = kp + rcv;
        }
        {
            float* redw = red + khalf * RED_HALF + jt * RED_STRIDE;
            redw[lane]      = fin[0];
            redw[lane + 32] = fin[1];
        }
        __syncthreads();

        float v = red[cjt * RED_STRIDE + cid] + red[RED_HALF + cjt * RED_STRIDE + cid];
        float val = tanh_fast(v + xr);
        g_H[(t + 1) & 1][b0 + cb][j0 + cc] = val;

        __syncthreads();
        if (tid == 0) st_rel(relp, (unsigned)(t + 1));

        out[out_base + (size_t)t * H_] = val;
        if (write_last && t == S_ - 1)
            out[(size_t)B_ * S_ * H_ + (size_t)(b0 + cb) * H_ + j0 + cc] = val;

        if (tid < 32) {
            while (ld_acq(pollp) < (unsigned)(t + 1)) { }
        }
        __syncthreads();
    }
}

// ---------------- launch ----------------
extern "C" void kernel_launch(void* const* d_in, const int* in_sizes, int n_in,
                              void* d_out, int out_size) {
    const float* X    = (const float*)d_in[0];
    const float* Wxh  = (const float*)d_in[1];
    const float* Whh  = (const float*)d_in[2];
    const float* bh   = (const float*)d_in[3];
    float* out        = (float*)d_out;

    conv_x_kernel<<<32768, 256>>>(X);
    conv_w_kernel<<<1024, 256>>>(Wxh);
    rnn_init_kernel<<<64, 256>>>();

    cudaFuncSetAttribute(gemm_bf16_kernel,
                         cudaFuncAttributeMaxDynamicSharedMemorySize,
                         GEMM_SMEM);
    dim3 gg(8, 256);
    gemm_bf16_kernel<<<gg, 256, GEMM_SMEM>>>(bh, out);

    cudaFuncSetAttribute(rnn_scan_kernel,
                         cudaFuncAttributeMaxDynamicSharedMemorySize,
                         RNN_SMEM_BYTES);
    int write_last = (out_size >= B_ * S_ * H_ + B_ * H_) ? 1 : 0;
    rnn_scan_kernel<<<NCTA, 256, RNN_SMEM_BYTES>>>(Whh, out, write_last);
}